// round 2
// baseline (speedup 1.0000x reference)
#include <cuda_runtime.h>
#include <cuda_bf16.h>

// Problem constants
#define B_  4
#define C_  256
#define H_  64
#define W_  64
#define O_  256
#define K_  3
#define K2_ 9
#define PAD_ 2
#define DIL_ 2
#define CK_ (C_ * K2_)          // 2304
#define HW_ (H_ * W_)           // 4096
#define OUT_MAIN (B_ * O_ * HW_)  // 4194304
#define DW_ELEMS (O_ * C_ * K2_)  // 589824

// Scratch (device globals; no allocation allowed)
__device__ float g_off[B_ * 18 * HW_];      // clipped offsets, (B,18,H,W)
__device__ float g_wt[CK_ * O_];            // W permuted: [(n*256+c)][o]

// ---------------------------------------------------------------------------
// Kernel A: offset conv (3x3, pad=1, dil=1), bias, clip to [-1,1]
// 64 blocks x 256 threads; one thread = one output pixel, 18 channels
// ---------------------------------------------------------------------------
__global__ __launch_bounds__(256) void offset_conv_kernel(
    const float* __restrict__ x, const float* __restrict__ ow,
    const float* __restrict__ ob)
{
    const int id = blockIdx.x * 256 + threadIdx.x;   // < 16384
    const int b  = id >> 12;
    const int hw = id & 4095;
    const int h  = hw >> 6;
    const int w  = hw & 63;

    float acc[18];
#pragma unroll
    for (int ch = 0; ch < 18; ch++) acc[ch] = ob[ch];

    __shared__ float sw[32 * 18 * 9];   // weights for a 32-channel chunk

    const float* xb = x + (size_t)b * C_ * HW_;

    for (int c0 = 0; c0 < C_; c0 += 32) {
        __syncthreads();
        // load weights: ow[ch][c][t], t = ky*3+kx -> sw[cc*162 + ch*9 + t]
        for (int i = threadIdx.x; i < 32 * 162; i += 256) {
            int cc = i / 162;
            int r  = i - cc * 162;
            int ch = r / 9;
            int t  = r - ch * 9;
            sw[i] = ow[ch * CK_ + (c0 + cc) * 9 + t];
        }
        __syncthreads();

        for (int cc = 0; cc < 32; cc++) {
            const float* xp = xb + (size_t)(c0 + cc) * HW_;
            float xv[9];
#pragma unroll
            for (int ky = 0; ky < 3; ky++) {
#pragma unroll
                for (int kx = 0; kx < 3; kx++) {
                    int yy = h + ky - 1;
                    int xx = w + kx - 1;
                    bool ok = (yy >= 0) & (yy < H_) & (xx >= 0) & (xx < W_);
                    xv[ky * 3 + kx] = ok ? xp[yy * W_ + xx] : 0.0f;
                }
            }
            const float* swc = sw + cc * 162;
#pragma unroll
            for (int ch = 0; ch < 18; ch++) {
#pragma unroll
                for (int t = 0; t < 9; t++)
                    acc[ch] = fmaf(swc[ch * 9 + t], xv[t], acc[ch]);
            }
        }
    }

#pragma unroll
    for (int ch = 0; ch < 18; ch++) {
        float v = acc[ch];
        v = fminf(fmaxf(v, -1.0f), 1.0f);
        g_off[((size_t)b * 18 + ch) * HW_ + hw] = v;
    }
}

// ---------------------------------------------------------------------------
// Kernel D: permute deform_w -> g_wt[(n*256+c)*256+o], and copy raw deform_w
// into the output tail (second element of the returned tuple).
// ---------------------------------------------------------------------------
__global__ __launch_bounds__(256) void permute_w_kernel(
    const float* __restrict__ dw, float* __restrict__ out_tail)
{
    int id = blockIdx.x * 256 + threadIdx.x;
    if (id >= DW_ELEMS) return;
    float v = dw[id];
    int o = id / CK_;
    int r = id - o * CK_;       // c*9+n
    int c = r / 9;
    int n = r - c * 9;
    g_wt[(n * C_ + c) * O_ + o] = v;
    out_tail[id] = v;
}

// ---------------------------------------------------------------------------
// Kernel B: fused deformable sampling + GEMM.
// One block per (b, h): BN=64 pixels (full row), BM=256 outputs, K=2304
// chunked by 16. 256 threads; thread microtile = 8 o x 8 pix.
// ---------------------------------------------------------------------------
__global__ __launch_bounds__(256) void deform_gemm_kernel(
    const float* __restrict__ x, const float* __restrict__ db,
    float* __restrict__ out)
{
    const int b = blockIdx.x >> 6;
    const int h = blockIdx.x & 63;

    __shared__ float4 Ws4[16][64];   // [kk][o/4]   16KB
    __shared__ float4 Cs4[16][16];   // [kk][pix/4] 4KB
    __shared__ int    sidx[9][64][4];
    __shared__ float  swt[9][64][4];

    const int tid = threadIdx.x;

    // ---- sampling metadata: per (tap n, pixel w): 4 corner idx + weights ----
    for (int task = tid; task < 9 * 64; task += 256) {
        int n = task >> 6;
        int w = task & 63;
        float dy = g_off[((size_t)b * 18 + 2 * n)     * HW_ + h * W_ + w];
        float dx = g_off[((size_t)b * 18 + 2 * n + 1) * HW_ + h * W_ + w];
        float py = dy + (float)(-PAD_ + (n / 3) * DIL_ + h);
        float px = dx + (float)(-PAD_ + (n % 3) * DIL_ + w);
        float y0f = floorf(py);
        float x0f = floorf(px);
        float ly1 = py - y0f, lx1 = px - x0f;
        float ly0 = 1.0f - ly1, lx0 = 1.0f - lx1;
        int y0 = (int)y0f, x0 = (int)x0f;
#pragma unroll
        for (int j = 0; j < 4; j++) {
            int yy = y0 + (j >> 1);
            int xx = x0 + (j & 1);
            float wgt = ((j >> 1) ? ly1 : ly0) * ((j & 1) ? lx1 : lx0);
            bool ok = (yy >= 0) & (yy < H_) & (xx >= 0) & (xx < W_);
            int yi = min(max(yy, 0), H_ - 1);
            int xi = min(max(xx, 0), W_ - 1);
            sidx[n][w][j] = yi * W_ + xi;
            swt[n][w][j]  = ok ? wgt : 0.0f;
        }
    }
    __syncthreads();

    // ---- GEMM main loop ----
    const int to = tid >> 3;   // 0..31 -> o block of 8
    const int tp = tid & 7;    // 0..7  -> pixel block of 8

    float acc[8][8];
#pragma unroll
    for (int i = 0; i < 8; i++)
#pragma unroll
        for (int j = 0; j < 8; j++) acc[i][j] = 0.0f;

    const float* xb = x + (size_t)b * C_ * HW_;
    float* Csf = (float*)Cs4;

    for (int n = 0; n < 9; n++) {
        for (int c0 = 0; c0 < C_; c0 += 16) {
            __syncthreads();
            // stage W chunk (coalesced float4 loads from g_wt)
            const float4* wt4 = (const float4*)(g_wt + (size_t)(n * C_ + c0) * O_);
            {
                int id4 = tid;
#pragma unroll
                for (int r = 0; r < 4; r++) {
                    int kk = id4 >> 6;
                    int o4 = id4 & 63;
                    Ws4[kk][o4] = wt4[kk * 64 + o4];
                    id4 += 256;
                }
            }
            // build cols chunk: Cs[kk][pix] = bilinear sample of channel c0+kk
            {
                int id = tid;
#pragma unroll
                for (int r = 0; r < 4; r++) {
                    int kk = id >> 6;
                    int pix = id & 63;
                    const float* xc = xb + (size_t)(c0 + kk) * HW_;
                    const int*   si = sidx[n][pix];
                    const float* sw2 = swt[n][pix];
                    float v = sw2[0] * __ldg(xc + si[0]);
                    v = fmaf(sw2[1], __ldg(xc + si[1]), v);
                    v = fmaf(sw2[2], __ldg(xc + si[2]), v);
                    v = fmaf(sw2[3], __ldg(xc + si[3]), v);
                    Csf[kk * 64 + pix] = v;
                    id += 256;
                }
            }
            __syncthreads();

#pragma unroll
            for (int kk = 0; kk < 16; kk++) {
                float4 w0 = Ws4[kk][to * 2];
                float4 w1 = Ws4[kk][to * 2 + 1];
                float4 ca = Cs4[kk][tp * 2];
                float4 cb = Cs4[kk][tp * 2 + 1];
                float wv[8] = {w0.x, w0.y, w0.z, w0.w, w1.x, w1.y, w1.z, w1.w};
                float cv[8] = {ca.x, ca.y, ca.z, ca.w, cb.x, cb.y, cb.z, cb.w};
#pragma unroll
                for (int i = 0; i < 8; i++)
#pragma unroll
                    for (int j = 0; j < 8; j++)
                        acc[i][j] = fmaf(wv[i], cv[j], acc[i][j]);
            }
        }
    }

    // ---- epilogue: bias + store ----
    const int o_base = to * 8;
    const int p_base = tp * 8;
#pragma unroll
    for (int i = 0; i < 8; i++) {
        float bias = db[o_base + i];
        float* op = out + ((size_t)b * O_ + o_base + i) * HW_ + h * W_ + p_base;
        float4 v0 = make_float4(acc[i][0] + bias, acc[i][1] + bias,
                                acc[i][2] + bias, acc[i][3] + bias);
        float4 v1 = make_float4(acc[i][4] + bias, acc[i][5] + bias,
                                acc[i][6] + bias, acc[i][7] + bias);
        ((float4*)op)[0] = v0;
        ((float4*)op)[1] = v1;
    }
}

// ---------------------------------------------------------------------------
extern "C" void kernel_launch(void* const* d_in, const int* in_sizes, int n_in,
                              void* d_out, int out_size)
{
    const float* x  = (const float*)d_in[0];   // (4,256,64,64)
    const float* ow = (const float*)d_in[1];   // (18,256,3,3)
    const float* ob = (const float*)d_in[2];   // (18,)
    const float* dw = (const float*)d_in[3];   // (256,256,3,3)
    const float* db = (const float*)d_in[4];   // (256,)
    float* out = (float*)d_out;

    // A: offset conv -> g_off
    offset_conv_kernel<<<64, 256>>>(x, ow, ob);
    // D: permute weights -> g_wt, copy deform_w into output tail
    permute_w_kernel<<<(DW_ELEMS + 255) / 256, 256>>>(dw, out + OUT_MAIN);
    // B: fused sample + GEMM -> out
    deform_gemm_kernel<<<B_ * H_, 256>>>(x, db, out);
}

// round 4
// speedup vs baseline: 3.1956x; 3.1956x over previous
#include <cuda_runtime.h>
#include <cuda_bf16.h>
#include <cstdint>

// Problem constants
#define B_  4
#define C_  256
#define H_  64
#define W_  64
#define O_  256
#define K2_ 9
#define PAD_ 2
#define DIL_ 2
#define CK_ (C_ * K2_)            // 2304
#define HW_ (H_ * W_)             // 4096
#define OUT_MAIN (B_ * O_ * HW_)  // 4194304
#define DW_ELEMS (O_ * C_ * K2_)  // 589824

#define SWZ(off) ((off) ^ (((off) >> 3) & 0x70))

// ---------------------------------------------------------------------------
// Scratch (device globals; no allocation allowed)
// ---------------------------------------------------------------------------
__device__ float g_off[B_ * 18 * HW_];            // clipped offsets (B,18,H,W)
__device__ float g_xT[B_ * HW_ * C_];             // x transposed: [b][hw][c]  (16MB)
__device__ unsigned char g_w[36 * 65536];         // bf16 hi/lo weight tiles, pre-swizzled

// ---------------------------------------------------------------------------
// mma.sync helpers (base-target tensor core path; tcgen05 unavailable on sm_103)
// ---------------------------------------------------------------------------
__device__ __forceinline__ void ldsm4(uint32_t* r, uint32_t addr) {
    asm volatile("ldmatrix.sync.aligned.m8n8.x4.shared.b16 {%0,%1,%2,%3}, [%4];"
        : "=r"(r[0]), "=r"(r[1]), "=r"(r[2]), "=r"(r[3]) : "r"(addr));
}
__device__ __forceinline__ void mma16816(float* c, const uint32_t* a, const uint32_t* b) {
    asm volatile("mma.sync.aligned.m16n8k16.row.col.f32.bf16.bf16.f32 "
        "{%0,%1,%2,%3}, {%4,%5,%6,%7}, {%8,%9}, {%0,%1,%2,%3};"
        : "+f"(c[0]), "+f"(c[1]), "+f"(c[2]), "+f"(c[3])
        : "r"(a[0]), "r"(a[1]), "r"(a[2]), "r"(a[3]), "r"(b[0]), "r"(b[1]));
}
__device__ __forceinline__ uint32_t smem_u32(const void* p) {
    uint32_t a;
    asm("{ .reg .u64 t; cvta.to.shared.u64 t, %1; cvt.u32.u64 %0, t; }"
        : "=r"(a) : "l"(p));
    return a;
}
__device__ __forceinline__ uint32_t pack_bf16(float a, float b) {
    return ((uint32_t)__bfloat16_as_ushort(__float2bfloat16(b)) << 16) |
           (uint32_t)__bfloat16_as_ushort(__float2bfloat16(a));
}

// ---------------------------------------------------------------------------
// Kernel T: transpose x (b,c,hw) -> g_xT (b,hw,c)
// ---------------------------------------------------------------------------
__global__ __launch_bounds__(256) void transpose_kernel(const float* __restrict__ x)
{
    __shared__ float ts[32][33];
    const int b = blockIdx.z, c0 = blockIdx.y * 32, hw0 = blockIdx.x * 32;
    const int tx = threadIdx.x, ty = threadIdx.y;  // 32 x 8
    const float* xb = x + (size_t)b * C_ * HW_;
#pragma unroll
    for (int i = 0; i < 4; i++)
        ts[ty + i * 8][tx] = xb[(size_t)(c0 + ty + i * 8) * HW_ + hw0 + tx];
    __syncthreads();
    float* dst = g_xT + (size_t)b * HW_ * C_;
#pragma unroll
    for (int i = 0; i < 4; i++)
        dst[(size_t)(hw0 + ty + i * 8) * C_ + c0 + tx] = ts[tx][ty + i * 8];
}

// ---------------------------------------------------------------------------
// Kernel A: offset conv (3x3, pad=1, dil=1) + bias + clip.
// 256 blocks (b,h) x 512 threads; 16-way channel split + smem reduction.
// ---------------------------------------------------------------------------
__global__ __launch_bounds__(512) void offset_conv2_kernel(
    const float* __restrict__ x, const float* __restrict__ ow,
    const float* __restrict__ ob)
{
    extern __shared__ float sm[];
    const int b = blockIdx.x >> 6;
    const int h = blockIdx.x & 63;
    const int tid = threadIdx.x;
    const int g = tid >> 5;
    const int wq = tid & 31;
    const int w0 = wq * 2;

    float acc[18][2];
#pragma unroll
    for (int ch = 0; ch < 18; ch++) { acc[ch][0] = 0.f; acc[ch][1] = 0.f; }

    for (int r = 0; r < 4; r++) {
        __syncthreads();
        for (int i = tid; i < 64 * 162; i += 512) {
            int cc = i / 162;
            int j  = i - cc * 162;
            int ch = j / 9;
            int t  = j - ch * 9;
            sm[i] = ow[ch * CK_ + (r * 64 + cc) * 9 + t];
        }
        __syncthreads();

#pragma unroll
        for (int q = 0; q < 4; q++) {
            const int cc = g * 4 + q;
            const int c  = r * 64 + cc;
            const float* xp = x + ((size_t)b * C_ + c) * HW_;
            float xv[3][4];
#pragma unroll
            for (int ry = 0; ry < 3; ry++) {
                int yy = h - 1 + ry;
                bool yok = (yy >= 0) & (yy < H_);
#pragma unroll
                for (int cx = 0; cx < 4; cx++) {
                    int xx = w0 - 1 + cx;
                    bool ok = yok & (xx >= 0) & (xx < W_);
                    xv[ry][cx] = ok ? __ldg(xp + yy * W_ + xx) : 0.0f;
                }
            }
            const float* wc = sm + cc * 162;
#pragma unroll
            for (int ch = 0; ch < 18; ch++) {
#pragma unroll
                for (int ky = 0; ky < 3; ky++) {
#pragma unroll
                    for (int kx = 0; kx < 3; kx++) {
                        float wv = wc[ch * 9 + ky * 3 + kx];
                        acc[ch][0] = fmaf(wv, xv[ky][kx],     acc[ch][0]);
                        acc[ch][1] = fmaf(wv, xv[ky][kx + 1], acc[ch][1]);
                    }
                }
            }
        }
    }
    __syncthreads();
#pragma unroll
    for (int ch = 0; ch < 18; ch++) {
        sm[(g * 18 + ch) * 64 + w0]     = acc[ch][0];
        sm[(g * 18 + ch) * 64 + w0 + 1] = acc[ch][1];
    }
    __syncthreads();
    for (int i = tid; i < 18 * 64; i += 512) {
        int ch = i >> 6;
        int w  = i & 63;
        float s = ob[ch];
#pragma unroll
        for (int gg = 0; gg < 16; gg++) s += sm[(gg * 18 + ch) * 64 + w];
        s = fminf(fmaxf(s, -1.0f), 1.0f);
        g_off[((size_t)b * 18 + ch) * HW_ + h * W_ + w] = s;
    }
}

// ---------------------------------------------------------------------------
// Kernel P: deform_w -> bf16 hi/lo pre-swizzled tiles + output-tail copy.
// Tile t = n*4+cc (tap n, 64-ch chunk cc): [comp][256 o rows][64 k bf16], SW128.
// ---------------------------------------------------------------------------
__global__ __launch_bounds__(256) void prep_w_kernel(
    const float* __restrict__ dw, float* __restrict__ out_tail)
{
    int id = blockIdx.x * 256 + threadIdx.x;
    if (id >= DW_ELEMS) return;
    out_tail[id] = dw[id];

    int k = id & 63;
    int o = (id >> 6) & 255;
    int t = id >> 14;            // 0..35
    int n = t >> 2;
    int cc = t & 3;
    int c = cc * 64 + k;
    float v = dw[o * CK_ + c * 9 + n];
    __nv_bfloat16 hi = __float2bfloat16(v);
    __nv_bfloat16 lo = __float2bfloat16(v - __bfloat162float(hi));
    uint32_t sw = SWZ((uint32_t)(o * 128 + k * 2));
    size_t base = (size_t)t * 65536;
    *(__nv_bfloat16*)(g_w + base + sw)         = hi;
    *(__nv_bfloat16*)(g_w + base + 32768 + sw) = lo;
}

// ---------------------------------------------------------------------------
// Kernel B: fused deform sampling + bf16-split mma.sync GEMM.
// Grid = 128 blocks (b, h2): N=128 pixels (2 rows), M=256 o, K=2304.
// 512 threads = 16 warps; warp tile 64(M) x 32(N); acc fp32 in regs.
// ---------------------------------------------------------------------------
#define OFF_A    0        // [comp][256][64] bf16 = 2 x 32KB
#define OFF_B    65536    // [comp][128][64] bf16 = 2 x 16KB
#define OFF_SWT  98304    // float [9][128][4]
#define OFF_SIDX 116736   // int   [9][128][4]  (pre-scaled hw*C_)
#define FUSED_SMEM 135168

__global__ __launch_bounds__(512, 1) void fused_deform_mma_kernel(
    const float* __restrict__ db, float* __restrict__ out)
{
    extern __shared__ char smem[];
    const uint32_t sb = smem_u32(smem);
    const int tid = threadIdx.x;
    const int wid = tid >> 5;
    const int lid = tid & 31;
    const int b  = blockIdx.x >> 5;
    const int h2 = blockIdx.x & 31;

    // ---- sampling metadata: 9 taps x 128 pixels -> 4 corner offsets + weights
    float* swt = (float*)(smem + OFF_SWT);
    int*   sidx = (int*)(smem + OFF_SIDX);
    for (int task = tid; task < 9 * 128; task += 512) {
        int n = task >> 7;
        int p = task & 127;
        int h = h2 * 2 + (p >> 6);
        int w = p & 63;
        float dy = g_off[((size_t)b * 18 + 2 * n)     * HW_ + h * W_ + w];
        float dx = g_off[((size_t)b * 18 + 2 * n + 1) * HW_ + h * W_ + w];
        float py = dy + (float)(-PAD_ + (n / 3) * DIL_ + h);
        float px = dx + (float)(-PAD_ + (n % 3) * DIL_ + w);
        float y0f = floorf(py);
        float x0f = floorf(px);
        float ly1 = py - y0f, lx1 = px - x0f;
        float ly0 = 1.0f - ly1, lx0 = 1.0f - lx1;
        int y0 = (int)y0f, x0 = (int)x0f;
#pragma unroll
        for (int j = 0; j < 4; j++) {
            int yy = y0 + (j >> 1);
            int xx = x0 + (j & 1);
            float wgt = ((j >> 1) ? ly1 : ly0) * ((j & 1) ? lx1 : lx0);
            bool ok = (yy >= 0) & (yy < H_) & (xx >= 0) & (xx < W_);
            int yi = min(max(yy, 0), H_ - 1);
            int xi = min(max(xx, 0), W_ - 1);
            sidx[task * 4 + j] = (yi * W_ + xi) * C_;
            swt [task * 4 + j] = ok ? wgt : 0.0f;
        }
    }

    const int wm = wid >> 2;                 // 0..3 : o block of 64
    const int wn = wid & 3;                  // 0..3 : pixel block of 32
    // per-lane ldmatrix row/col components
    const int aRow = wm * 64 + (lid & 15);
    const int aKad = (lid >> 4) * 16;
    const int bRow = wn * 32 + ((lid >> 4) & 1) * 8 + (lid & 7);
    const int bKad = ((lid >> 3) & 1) * 16;

    float acc[4][4][4];
#pragma unroll
    for (int i = 0; i < 4; i++)
#pragma unroll
        for (int j = 0; j < 4; j++)
#pragma unroll
            for (int q = 0; q < 4; q++) acc[i][j][q] = 0.0f;

    const float* xT = g_xT + (size_t)b * HW_ * C_;

    for (int t = 0; t < 36; t++) {
        const int n  = t >> 2;
        const int c0 = (t & 3) * 64;
        __syncthreads();

        // stage A: 64KB straight copy (pre-swizzled in global)
        {
            const float4* src = (const float4*)(g_w + (size_t)t * 65536);
            float4* dstA = (float4*)(smem + OFF_A);
#pragma unroll
            for (int i = 0; i < 8; i++) dstA[tid + i * 512] = __ldg(src + tid + i * 512);
        }
        // stage B: bilinear sample (coalesced gathers from xT) -> bf16 hi/lo
#pragma unroll
        for (int it = 0; it < 4; it++) {
            int id = tid + it * 512;          // 2048 tasks
            int ch4 = id & 15;                // channel group of 4
            int p   = id >> 4;                // pixel 0..127
            const int4   si = *(const int4*)  (sidx + (n * 128 + p) * 4);
            const float4 wt = *(const float4*)(swt  + (n * 128 + p) * 4);
            const float* xb = xT + c0 + ch4 * 4;
            float4 v0 = __ldg((const float4*)(xb + si.x));
            float4 v1 = __ldg((const float4*)(xb + si.y));
            float4 v2 = __ldg((const float4*)(xb + si.z));
            float4 v3 = __ldg((const float4*)(xb + si.w));
            float s0 = wt.x * v0.x + wt.y * v1.x + wt.z * v2.x + wt.w * v3.x;
            float s1 = wt.x * v0.y + wt.y * v1.y + wt.z * v2.y + wt.w * v3.y;
            float s2 = wt.x * v0.z + wt.y * v1.z + wt.z * v2.z + wt.w * v3.z;
            float s3 = wt.x * v0.w + wt.y * v1.w + wt.z * v2.w + wt.w * v3.w;
            // hi
            uint32_t h0 = pack_bf16(s0, s1);
            uint32_t h1 = pack_bf16(s2, s3);
            // lo = residual
            float r0 = s0 - __bfloat162float(__float2bfloat16(s0));
            float r1 = s1 - __bfloat162float(__float2bfloat16(s1));
            float r2 = s2 - __bfloat162float(__float2bfloat16(s2));
            float r3 = s3 - __bfloat162float(__float2bfloat16(s3));
            uint32_t l0 = pack_bf16(r0, r1);
            uint32_t l1 = pack_bf16(r2, r3);
            uint32_t sw = SWZ((uint32_t)(p * 128 + ch4 * 8));
            *(uint2*)(smem + OFF_B + sw)         = make_uint2(h0, h1);
            *(uint2*)(smem + OFF_B + 16384 + sw) = make_uint2(l0, l1);
        }
        __syncthreads();

        // ---- MMA: 4 ksteps x (Ah*Bh + Ah*Bl + Al*Bh) ----
        const uint32_t aBaseH = sb + OFF_A;
        const uint32_t aBaseL = sb + OFF_A + 32768;
        const uint32_t bBaseH = sb + OFF_B;
        const uint32_t bBaseL = sb + OFF_B + 16384;
#pragma unroll
        for (int ks = 0; ks < 4; ks++) {
            uint32_t bh[8], bl[8];
#pragma unroll
            for (int pair = 0; pair < 2; pair++) {
                uint32_t off = SWZ((uint32_t)((bRow + pair * 16) * 128 + ks * 32 + bKad));
                ldsm4(bh + pair * 4, bBaseH + off);
                ldsm4(bl + pair * 4, bBaseL + off);
            }
#pragma unroll
            for (int mt = 0; mt < 4; mt++) {
                uint32_t offA = SWZ((uint32_t)((aRow + mt * 16) * 128 + ks * 32 + aKad));
                uint32_t ah[4], al[4];
                ldsm4(ah, aBaseH + offA);
#pragma unroll
                for (int j = 0; j < 4; j++) {
                    mma16816(acc[mt][j], ah, bh + j * 2);
                    mma16816(acc[mt][j], ah, bl + j * 2);
                }
                ldsm4(al, aBaseL + offA);
#pragma unroll
                for (int j = 0; j < 4; j++)
                    mma16816(acc[mt][j], al, bh + j * 2);
            }
        }
    }

    // ---- epilogue: bias + store ----
#pragma unroll
    for (int mt = 0; mt < 4; mt++) {
        int o0 = wm * 64 + mt * 16 + (lid >> 2);
        float b0v = __ldg(db + o0);
        float b1v = __ldg(db + o0 + 8);
#pragma unroll
        for (int j = 0; j < 4; j++) {
            int pix = wn * 32 + j * 8 + (lid & 3) * 2;
            int row = pix >> 6, col = pix & 63;
            float* p0 = out + ((size_t)(b * O_ + o0)) * HW_
                            + (size_t)(h2 * 2 + row) * W_ + col;
            *(float2*)p0 = make_float2(acc[mt][j][0] + b0v, acc[mt][j][1] + b0v);
            float* p1 = p0 + (size_t)8 * HW_;
            *(float2*)p1 = make_float2(acc[mt][j][2] + b1v, acc[mt][j][3] + b1v);
        }
    }
}

// ---------------------------------------------------------------------------
extern "C" void kernel_launch(void* const* d_in, const int* in_sizes, int n_in,
                              void* d_out, int out_size)
{
    const float* x  = (const float*)d_in[0];   // (4,256,64,64)
    const float* ow = (const float*)d_in[1];   // (18,256,3,3)
    const float* ob = (const float*)d_in[2];   // (18,)
    const float* dw = (const float*)d_in[3];   // (256,256,3,3)
    const float* db = (const float*)d_in[4];   // (256,)
    float* out = (float*)d_out;

    cudaFuncSetAttribute(offset_conv2_kernel,
                         cudaFuncAttributeMaxDynamicSharedMemorySize, 73728);
    cudaFuncSetAttribute(fused_deform_mma_kernel,
                         cudaFuncAttributeMaxDynamicSharedMemorySize, FUSED_SMEM);

    dim3 tgrid(128, 8, 4), tblk(32, 8);
    transpose_kernel<<<tgrid, tblk>>>(x);
    offset_conv2_kernel<<<B_ * H_, 512, 73728>>>(x, ow, ob);
    prep_w_kernel<<<(DW_ELEMS + 255) / 256, 256>>>(dw, out + OUT_MAIN);
    fused_deform_mma_kernel<<<B_ * 32, 512, FUSED_SMEM>>>(db, out);
}

// round 6
// speedup vs baseline: 5.4534x; 1.7065x over previous
#include <cuda_runtime.h>
#include <cuda_bf16.h>
#include <cstdint>

// Problem constants
#define B_  4
#define C_  256
#define H_  64
#define W_  64
#define O_  256
#define K2_ 9
#define PAD_ 2
#define DIL_ 2
#define CK_ (C_ * K2_)            // 2304
#define HW_ (H_ * W_)             // 4096
#define OUT_MAIN (B_ * O_ * HW_)  // 4194304
#define DW_ELEMS (O_ * C_ * K2_)  // 589824

#define SWZ(off) ((off) ^ (((off) >> 3) & 0x70))

// ---------------------------------------------------------------------------
// Scratch (device globals; no allocation allowed)
// ---------------------------------------------------------------------------
__device__ float g_off[B_ * 18 * HW_];            // clipped offsets (B,18,H,W)
__device__ float g_xT[B_ * HW_ * C_];             // x transposed: [b][hw][c]
__device__ unsigned char g_w[36 * 65536];         // bf16 hi/lo weight tiles, pre-swizzled

// ---------------------------------------------------------------------------
// helpers
// ---------------------------------------------------------------------------
__device__ __forceinline__ void ldsm4(uint32_t* r, uint32_t addr) {
    asm volatile("ldmatrix.sync.aligned.m8n8.x4.shared.b16 {%0,%1,%2,%3}, [%4];"
        : "=r"(r[0]), "=r"(r[1]), "=r"(r[2]), "=r"(r[3]) : "r"(addr));
}
__device__ __forceinline__ void mma16816(float* c, const uint32_t* a, const uint32_t* b) {
    asm volatile("mma.sync.aligned.m16n8k16.row.col.f32.bf16.bf16.f32 "
        "{%0,%1,%2,%3}, {%4,%5,%6,%7}, {%8,%9}, {%0,%1,%2,%3};"
        : "+f"(c[0]), "+f"(c[1]), "+f"(c[2]), "+f"(c[3])
        : "r"(a[0]), "r"(a[1]), "r"(a[2]), "r"(a[3]), "r"(b[0]), "r"(b[1]));
}
__device__ __forceinline__ uint32_t smem_u32(const void* p) {
    uint32_t a;
    asm("{ .reg .u64 t; cvta.to.shared.u64 t, %1; cvt.u32.u64 %0, t; }"
        : "=r"(a) : "l"(p));
    return a;
}
__device__ __forceinline__ uint32_t pack_bf16(float a, float b) {
    return ((uint32_t)__bfloat16_as_ushort(__float2bfloat16(b)) << 16) |
           (uint32_t)__bfloat16_as_ushort(__float2bfloat16(a));
}
__device__ __forceinline__ void cpasync16(uint32_t dst, const void* src) {
    asm volatile("cp.async.cg.shared.global [%0], [%1], 16;"
        :: "r"(dst), "l"(src) : "memory");
}

// ---------------------------------------------------------------------------
// Merged prologue kernel: roles by blockIdx.x (all 256 threads)
//   [0,4096)      : transpose x -> g_xT (32x32 tiles)
//   [4096,4352)   : offset conv (3x3 pad1 dil1) + bias + clip -> g_off
//   [4352,6656)   : weight prep (bf16 hi/lo, pre-swizzled) + output-tail copy
// ---------------------------------------------------------------------------
#define NB_T 4096
#define NB_O 256
#define NB_P 2304
#define PRO_SMEM 41472

__global__ __launch_bounds__(256) void prologue_kernel(
    const float* __restrict__ x, const float* __restrict__ ow,
    const float* __restrict__ ob, const float* __restrict__ dw,
    float* __restrict__ out_tail)
{
    extern __shared__ float sm[];
    const int bid = blockIdx.x;
    const int tid = threadIdx.x;

    if (bid < NB_T) {
        // ---- transpose ----
        __shared__ float ts[32][33];
        const int b = bid >> 10;
        const int tile = bid & 1023;
        const int c0 = (tile >> 7) * 32;
        const int hw0 = (tile & 127) * 32;
        const int tx = tid & 31, ty = tid >> 5;
        const float* xb = x + (size_t)b * C_ * HW_;
#pragma unroll
        for (int i = 0; i < 4; i++)
            ts[ty + i * 8][tx] = __ldg(xb + (size_t)(c0 + ty + i * 8) * HW_ + hw0 + tx);
        __syncthreads();
        float* dst = g_xT + (size_t)b * HW_ * C_;
#pragma unroll
        for (int i = 0; i < 4; i++)
            dst[(size_t)(hw0 + ty + i * 8) * C_ + c0 + tx] = ts[tx][ty + i * 8];
        return;
    }

    if (bid < NB_T + NB_O) {
        // ---- offset conv ----
        const int b2 = bid - NB_T;
        const int b = b2 >> 6;
        const int h = b2 & 63;
        const int g = tid >> 5;       // 0..7
        const int wq = tid & 31;
        const int w0 = wq * 2;

        float acc[18][2];
#pragma unroll
        for (int ch = 0; ch < 18; ch++) { acc[ch][0] = 0.f; acc[ch][1] = 0.f; }

        for (int r = 0; r < 4; r++) {
            __syncthreads();
            for (int i = tid; i < 64 * 162; i += 256) {
                int cc = i / 162;
                int j  = i - cc * 162;
                int ch = j / 9;
                int t  = j - ch * 9;
                sm[i] = ow[ch * CK_ + (r * 64 + cc) * 9 + t];
            }
            __syncthreads();

#pragma unroll
            for (int q = 0; q < 8; q++) {
                const int cc = g * 8 + q;
                const int c  = r * 64 + cc;
                const float* xp = x + ((size_t)b * C_ + c) * HW_;
                float xv[3][4];
#pragma unroll
                for (int ry = 0; ry < 3; ry++) {
                    int yy = h - 1 + ry;
                    bool yok = (yy >= 0) & (yy < H_);
#pragma unroll
                    for (int cx = 0; cx < 4; cx++) {
                        int xx = w0 - 1 + cx;
                        bool ok = yok & (xx >= 0) & (xx < W_);
                        xv[ry][cx] = ok ? __ldg(xp + yy * W_ + xx) : 0.0f;
                    }
                }
                const float* wc = sm + cc * 162;
#pragma unroll
                for (int ch = 0; ch < 18; ch++) {
#pragma unroll
                    for (int ky = 0; ky < 3; ky++) {
#pragma unroll
                        for (int kx = 0; kx < 3; kx++) {
                            float wv = wc[ch * 9 + ky * 3 + kx];
                            acc[ch][0] = fmaf(wv, xv[ky][kx],     acc[ch][0]);
                            acc[ch][1] = fmaf(wv, xv[ky][kx + 1], acc[ch][1]);
                        }
                    }
                }
            }
        }
        __syncthreads();
#pragma unroll
        for (int ch = 0; ch < 18; ch++) {
            sm[(g * 18 + ch) * 64 + w0]     = acc[ch][0];
            sm[(g * 18 + ch) * 64 + w0 + 1] = acc[ch][1];
        }
        __syncthreads();
        for (int i = tid; i < 18 * 64; i += 256) {
            int ch = i >> 6;
            int w  = i & 63;
            float s = ob[ch];
#pragma unroll
            for (int gg = 0; gg < 8; gg++) s += sm[(gg * 18 + ch) * 64 + w];
            s = fminf(fmaxf(s, -1.0f), 1.0f);
            g_off[((size_t)b * 18 + ch) * HW_ + h * W_ + w] = s;
        }
        return;
    }

    // ---- weight prep + tail copy ----
    {
        int id = (bid - NB_T - NB_O) * 256 + tid;
        out_tail[id] = dw[id];
        int k = id & 63;
        int o = (id >> 6) & 255;
        int t = id >> 14;            // 0..35
        int n = t >> 2;
        int cc = t & 3;
        int c = cc * 64 + k;
        float v = __ldg(dw + o * CK_ + c * 9 + n);
        __nv_bfloat16 hi = __float2bfloat16(v);
        __nv_bfloat16 lo = __float2bfloat16(v - __bfloat162float(hi));
        uint32_t sw = SWZ((uint32_t)(o * 128 + k * 2));
        size_t base = (size_t)t * 65536;
        *(__nv_bfloat16*)(g_w + base + sw)         = hi;
        *(__nv_bfloat16*)(g_w + base + 32768 + sw) = lo;
    }
}

// ---------------------------------------------------------------------------
// Fused deform sampling + bf16-split mma.sync GEMM, software pipelined.
// Grid = 128 blocks (b, h2): N=128 pixels (2 rows), M=256 o, K=2304 (36 x 64).
// Double-buffered A (cp.async) and B (register-gather overlapped with MMA).
// Race-free barrier schedule:
//   loop t:  bar1 (old-buffer reads done everywhere)
//            issue A(t+1) cp.async; commit; wait_group(A(t) landed for self)
//            bar2 (A(t) landed everywhere; B(t) STS visible)
//            4 phases: gather(t+1) -> MMA kstep(t) -> pack/STS B(t+1)
// ---------------------------------------------------------------------------
#define OFF_A    0        // 2 buf x [2 comp][256][64] bf16 = 2 x 65536
#define OFF_B    131072   // 2 buf x [2 comp][128][64] bf16 = 2 x 32768
#define OFF_SWT  196608   // float [9*128][4]  = 18432
#define OFF_SIDX 215040   // short [9*128][4]  = 9216
#define FUSED_SMEM 224256

__global__ __launch_bounds__(512, 1) void fused_deform_mma_kernel(
    const float* __restrict__ db, float* __restrict__ out)
{
    extern __shared__ char smem[];
    const uint32_t sb = smem_u32(smem);
    const int tid = threadIdx.x;
    const int wid = tid >> 5;
    const int lid = tid & 31;
    const int b  = blockIdx.x >> 5;
    const int h2 = blockIdx.x & 31;

    // ---- sampling metadata: 9 taps x 128 pixels ----
    float* swt  = (float*)(smem + OFF_SWT);
    short* sidx = (short*)(smem + OFF_SIDX);
    for (int task = tid; task < 9 * 128; task += 512) {
        int n = task >> 7;
        int p = task & 127;
        int h = h2 * 2 + (p >> 6);
        int w = p & 63;
        float dy = g_off[((size_t)b * 18 + 2 * n)     * HW_ + h * W_ + w];
        float dx = g_off[((size_t)b * 18 + 2 * n + 1) * HW_ + h * W_ + w];
        float py = dy + (float)(-PAD_ + (n / 3) * DIL_ + h);
        float px = dx + (float)(-PAD_ + (n % 3) * DIL_ + w);
        float y0f = floorf(py);
        float x0f = floorf(px);
        float ly1 = py - y0f, lx1 = px - x0f;
        float ly0 = 1.0f - ly1, lx0 = 1.0f - lx1;
        int y0 = (int)y0f, x0 = (int)x0f;
#pragma unroll
        for (int j = 0; j < 4; j++) {
            int yy = y0 + (j >> 1);
            int xx = x0 + (j & 1);
            float wgt = ((j >> 1) ? ly1 : ly0) * ((j & 1) ? lx1 : lx0);
            bool ok = (yy >= 0) & (yy < H_) & (xx >= 0) & (xx < W_);
            int yi = min(max(yy, 0), H_ - 1);
            int xi = min(max(xx, 0), W_ - 1);
            sidx[task * 4 + j] = (short)(yi * W_ + xi);
            swt [task * 4 + j] = ok ? wgt : 0.0f;
        }
    }
    __syncthreads();

    const float* xT = g_xT + (size_t)b * HW_ * C_;
    const int ch4 = tid & 15;          // channel group of 4 (fixed per thread)
    const int pix = tid >> 4;          // base pixel selector

    const int wm = wid >> 2;
    const int wn = wid & 3;
    const int aRow = wm * 64 + (lid & 15);
    const int aKad = (lid >> 4) * 16;
    const int bRow = wn * 32 + ((lid >> 4) & 1) * 8 + (lid & 7);
    const int bKad = ((lid >> 3) & 1) * 16;

    float acc[4][4][4];
#pragma unroll
    for (int i = 0; i < 4; i++)
#pragma unroll
        for (int j = 0; j < 4; j++)
#pragma unroll
            for (int q = 0; q < 4; q++) acc[i][j][q] = 0.0f;

    // ---- prologue: stage chunk 0 ----
    {
        uint32_t dstA = sb + OFF_A;
        const char* srcA = (const char*)g_w;
#pragma unroll
        for (int i = 0; i < 8; i++)
            cpasync16(dstA + (tid + i * 512) * 16, srcA + (size_t)(tid + i * 512) * 16);
        asm volatile("cp.async.commit_group;" ::: "memory");
#pragma unroll
        for (int ph = 0; ph < 4; ph++) {
            int id = tid + ph * 512;
            int c4 = id & 15;
            int p  = id >> 4;
            const float4 wt = *(const float4*)(swt + p * 4);
            const short* si = sidx + p * 4;
            const float* xb = xT + c4 * 4;
            float4 v0 = __ldg((const float4*)(xb + ((int)si[0] << 8)));
            float4 v1 = __ldg((const float4*)(xb + ((int)si[1] << 8)));
            float4 v2 = __ldg((const float4*)(xb + ((int)si[2] << 8)));
            float4 v3 = __ldg((const float4*)(xb + ((int)si[3] << 8)));
            float s0 = wt.x * v0.x + wt.y * v1.x + wt.z * v2.x + wt.w * v3.x;
            float s1 = wt.x * v0.y + wt.y * v1.y + wt.z * v2.y + wt.w * v3.y;
            float s2 = wt.x * v0.z + wt.y * v1.z + wt.z * v2.z + wt.w * v3.z;
            float s3 = wt.x * v0.w + wt.y * v1.w + wt.z * v2.w + wt.w * v3.w;
            uint32_t h0 = pack_bf16(s0, s1), h1 = pack_bf16(s2, s3);
            float r0 = s0 - __bfloat162float(__float2bfloat16(s0));
            float r1 = s1 - __bfloat162float(__float2bfloat16(s1));
            float r2 = s2 - __bfloat162float(__float2bfloat16(s2));
            float r3 = s3 - __bfloat162float(__float2bfloat16(s3));
            uint32_t l0 = pack_bf16(r0, r1), l1 = pack_bf16(r2, r3);
            uint32_t sw = SWZ((uint32_t)(p * 128 + c4 * 8));
            *(uint2*)(smem + OFF_B + sw)         = make_uint2(h0, h1);
            *(uint2*)(smem + OFF_B + 16384 + sw) = make_uint2(l0, l1);
        }
    }

    for (int t = 0; t < 36; t++) {
        const uint32_t bufT = (uint32_t)(t & 1);
        const uint32_t bufN = bufT ^ 1;
        const bool more = (t < 35);

        // bar1: all reads of buffer bufN's OLD content (A(t-1)/B(t-1)) complete
        __syncthreads();

        if (more) {
            uint32_t dstA = sb + OFF_A + bufN * 65536;
            const char* srcA = (const char*)(g_w + (size_t)(t + 1) * 65536);
#pragma unroll
            for (int i = 0; i < 8; i++)
                cpasync16(dstA + (tid + i * 512) * 16, srcA + (size_t)(tid + i * 512) * 16);
            asm volatile("cp.async.commit_group;" ::: "memory");
            asm volatile("cp.async.wait_group 1;" ::: "memory");
        } else {
            asm volatile("cp.async.wait_group 0;" ::: "memory");
        }

        // bar2: everyone's A(t) landed; B(t) STS from iter t-1 visible
        __syncthreads();

        const uint32_t aBaseH = sb + OFF_A + bufT * 65536;
        const uint32_t aBaseL = aBaseH + 32768;
        const uint32_t bBaseH = sb + OFF_B + bufT * 32768;
        const uint32_t bBaseL = bBaseH + 16384;
        char* bDst = smem + OFF_B + bufN * 32768;

        const int nN = (t + 1) >> 2;
        const int cN = ((t + 1) & 3) * 64;

#pragma unroll
        for (int ph = 0; ph < 4; ph++) {
            float4 v0, v1, v2, v3; float4 wt;
            int p = (pix + ph * 32) & 127;
            if (more) {
                int task = nN * 128 + p;
                wt = *(const float4*)(swt + task * 4);
                const short* si = sidx + task * 4;
                const float* xb = xT + cN + ch4 * 4;
                v0 = __ldg((const float4*)(xb + ((int)si[0] << 8)));
                v1 = __ldg((const float4*)(xb + ((int)si[1] << 8)));
                v2 = __ldg((const float4*)(xb + ((int)si[2] << 8)));
                v3 = __ldg((const float4*)(xb + ((int)si[3] << 8)));
            }

            // MMA k-step ph of chunk t
            {
                uint32_t bh[8], bl[8];
#pragma unroll
                for (int pair = 0; pair < 2; pair++) {
                    uint32_t off = SWZ((uint32_t)((bRow + pair * 16) * 128 + ph * 32 + bKad));
                    ldsm4(bh + pair * 4, bBaseH + off);
                    ldsm4(bl + pair * 4, bBaseL + off);
                }
#pragma unroll
                for (int mt = 0; mt < 4; mt++) {
                    uint32_t offA = SWZ((uint32_t)((aRow + mt * 16) * 128 + ph * 32 + aKad));
                    uint32_t ah[4], al[4];
                    ldsm4(ah, aBaseH + offA);
#pragma unroll
                    for (int j = 0; j < 4; j++) {
                        mma16816(acc[mt][j], ah, bh + j * 2);
                        mma16816(acc[mt][j], ah, bl + j * 2);
                    }
                    ldsm4(al, aBaseL + offA);
#pragma unroll
                    for (int j = 0; j < 4; j++)
                        mma16816(acc[mt][j], al, bh + j * 2);
                }
            }

            if (more) {
                float s0 = wt.x * v0.x + wt.y * v1.x + wt.z * v2.x + wt.w * v3.x;
                float s1 = wt.x * v0.y + wt.y * v1.y + wt.z * v2.y + wt.w * v3.y;
                float s2 = wt.x * v0.z + wt.y * v1.z + wt.z * v2.z + wt.w * v3.z;
                float s3 = wt.x * v0.w + wt.y * v1.w + wt.z * v2.w + wt.w * v3.w;
                uint32_t h0 = pack_bf16(s0, s1), h1 = pack_bf16(s2, s3);
                float r0 = s0 - __bfloat162float(__float2bfloat16(s0));
                float r1 = s1 - __bfloat162float(__float2bfloat16(s1));
                float r2 = s2 - __bfloat162float(__float2bfloat16(s2));
                float r3 = s3 - __bfloat162float(__float2bfloat16(s3));
                uint32_t l0 = pack_bf16(r0, r1), l1 = pack_bf16(r2, r3);
                uint32_t sw = SWZ((uint32_t)(p * 128 + ch4 * 8));
                *(uint2*)(bDst + sw)         = make_uint2(h0, h1);
                *(uint2*)(bDst + 16384 + sw) = make_uint2(l0, l1);
            }
        }
    }

    // ---- epilogue: bias + store ----
#pragma unroll
    for (int mt = 0; mt < 4; mt++) {
        int o0 = wm * 64 + mt * 16 + (lid >> 2);
        float b0v = __ldg(db + o0);
        float b1v = __ldg(db + o0 + 8);
#pragma unroll
        for (int j = 0; j < 4; j++) {
            int pixel = wn * 32 + j * 8 + (lid & 3) * 2;
            int row = pixel >> 6, col = pixel & 63;
            float* p0 = out + ((size_t)(b * O_ + o0)) * HW_
                            + (size_t)(h2 * 2 + row) * W_ + col;
            *(float2*)p0 = make_float2(acc[mt][j][0] + b0v, acc[mt][j][1] + b0v);
            float* p1 = p0 + (size_t)8 * HW_;
            *(float2*)p1 = make_float2(acc[mt][j][2] + b1v, acc[mt][j][3] + b1v);
        }
    }
}

// ---------------------------------------------------------------------------
extern "C" void kernel_launch(void* const* d_in, const int* in_sizes, int n_in,
                              void* d_out, int out_size)
{
    const float* x  = (const float*)d_in[0];
    const float* ow = (const float*)d_in[1];
    const float* ob = (const float*)d_in[2];
    const float* dw = (const float*)d_in[3];
    const float* db = (const float*)d_in[4];
    float* out = (float*)d_out;

    cudaFuncSetAttribute(prologue_kernel,
                         cudaFuncAttributeMaxDynamicSharedMemorySize, PRO_SMEM);
    cudaFuncSetAttribute(fused_deform_mma_kernel,
                         cudaFuncAttributeMaxDynamicSharedMemorySize, FUSED_SMEM);

    prologue_kernel<<<NB_T + NB_O + NB_P, 256, PRO_SMEM>>>(x, ow, ob, dw, out + OUT_MAIN);
    fused_deform_mma_kernel<<<B_ * 32, 512, FUSED_SMEM>>>(db, out);
}